// round 7
// baseline (speedup 1.0000x reference)
#include <cuda_runtime.h>
#include <cuda_bf16.h>
#include <cstdint>

#define DD 64
#define LL 128
#define KROWS 8192
#define MROWS 64
#define NBLK (KROWS/MROWS)   // 128 CTAs
#define NTHR 512

typedef unsigned int u32;

// smem byte offsets
#define SM_A0H 0          // h buf0 hi: 64 rows x 128B
#define SM_A0L 8192
#define SM_A1H 16384
#define SM_A1L 24576
#define SM_BH  32768      // B hi: 256 n-rows x 128B
#define SM_BL  65536
#define SM_X   98304      // x: 64 x 129 floats = 33024B
#define SM_CA  131328     // a consts, 256 floats
#define SM_CB  132352     // cb consts, 256 floats
#define SM_RED 133376     // 128 floats
#define SM_TOT 133952

__device__ float g_a[256];
__device__ float g_cb[256];
__device__ __nv_bfloat16 g_Bhi[256*64];
__device__ __nv_bfloat16 g_Blo[256*64];
__device__ float g_acc[128];

__device__ __forceinline__ float fexp(float x){
    x = fmaxf(fminf(x, 30.f), -30.f);
    return __expf(x);
}
__device__ __forceinline__ float sigf(float x){
    return __fdividef(1.0f, 1.0f + fexp(-x));
}
__device__ __forceinline__ float tanhp(float x){
    return 2.0f * __fdividef(1.0f, 1.0f + fexp(-2.0f*x)) - 1.0f;
}

__device__ __forceinline__ void mma_bf16(float* c, const u32* a, const u32* b){
    asm volatile("mma.sync.aligned.m16n8k16.row.col.f32.bf16.bf16.f32 "
        "{%0,%1,%2,%3}, {%4,%5,%6,%7}, {%8,%9}, {%0,%1,%2,%3};\n"
        : "+f"(c[0]),"+f"(c[1]),"+f"(c[2]),"+f"(c[3])
        : "r"(a[0]),"r"(a[1]),"r"(a[2]),"r"(a[3]), "r"(b[0]),"r"(b[1]));
}

// ---------- prep: collapsed input proj + reordered, pre-swizzled split-bf16 W_hh^T ----------
// Column order: n = wn*64 + j*8 + c, j in 0..7; gate G = j>>1; dl = (j&1)*8+c; d = wn*16+dl.
__global__ void prep_kernel(const float* __restrict__ W_ih, const float* __restrict__ W_num,
                            const float* __restrict__ b_num, const float* __restrict__ b_ih,
                            const float* __restrict__ b_hh, const float* __restrict__ W_hh){
    int n = threadIdx.x;            // 0..255
    int wn = n >> 6;                // n-quarter
    int rem = n & 63;
    int j = rem >> 3;
    int c = rem & 7;
    int G = j >> 1;
    int dl = (j & 1)*8 + c;
    int d  = wn*16 + dl;
    int wr = G*64 + d;
    float sa = 0.f, sc = 0.f;
    #pragma unroll 8
    for (int k = 0; k < DD; k++){
        float w = W_ih[wr*(2*DD) + k];
        sa += w * W_num[k];
        sc += w * b_num[k];
    }
    g_a[n]  = sa;
    g_cb[n] = sc + b_ih[wr] + b_hh[wr];
    #pragma unroll 8
    for (int k = 0; k < DD; k++){
        float w = W_hh[wr*DD + k];
        __nv_bfloat16 hi = __float2bfloat16(w);
        __nv_bfloat16 lo = __float2bfloat16(w - __bfloat162float(hi));
        u32 off = (u32)n*128 + (u32)k*2;
        u32 sw  = off ^ (((u32)n & 7u) << 4);
        g_Bhi[sw >> 1] = hi;
        g_Blo[sw >> 1] = lo;
    }
    if (n < 128) g_acc[n] = 0.f;
}

// ---------- main LSTM: warp-level HMMA, 16 warps ----------
__global__ void __launch_bounds__(NTHR,1)
lstm_kernel(const float* __restrict__ x,
            const float* __restrict__ W_aout, const float* __restrict__ b_aout,
            const float* __restrict__ W_fh,  const float* __restrict__ b_fh){
    extern __shared__ char sm[];
    const int tid  = threadIdx.x;
    const int wid  = tid >> 5;
    const int lane = tid & 31;
    const int g    = lane >> 2;      // group 0..7
    const int tq   = lane & 3;       // quad  0..3
    const int mt   = wid & 3;        // m-tile 0..3 (rows mt*16..)
    const int wn   = wid >> 2;       // n-quarter 0..3
    const u32 xorv = (u32)g << 4;
    const int r0   = blockIdx.x * MROWS;

    float* sXf = (float*)(sm + SM_X);
    float* sCa = (float*)(sm + SM_CA);
    float* sCb = (float*)(sm + SM_CB);
    float* sRd = (float*)(sm + SM_RED);

    // ---- init ----
    {
        uint4* db = (uint4*)(sm + SM_BH);
        const uint4* sb = (const uint4*)g_Bhi;
        for (int i = tid; i < 2048; i += NTHR) db[i] = sb[i];
        uint4* dl2 = (uint4*)(sm + SM_BL);
        const uint4* sl = (const uint4*)g_Blo;
        for (int i = tid; i < 2048; i += NTHR) dl2[i] = sl[i];
        uint4 z = make_uint4(0,0,0,0);
        uint4* da = (uint4*)(sm + SM_A0H);
        for (int i = tid; i < 2048; i += NTHR) da[i] = z;       // all 4 A buffers (32KB)
        for (int idx = tid; idx < MROWS*LL; idx += NTHR){
            int rr = idx >> 7, tt = idx & 127;
            sXf[rr*129 + tt] = x[(size_t)(r0 + rr)*LL + tt];
        }
        if (tid < 256){ sCa[tid] = g_a[tid]; sCb[tid] = g_cb[tid]; }
        if (tid < 128) sRd[tid] = 0.f;
    }
    __syncthreads();

    float creg[8];
    #pragma unroll
    for (int i = 0; i < 8; i++) creg[i] = 0.f;

    const char* Bh0 = sm + SM_BH + (size_t)((wn*64 + g) * 128);
    const char* Bl0 = sm + SM_BL + (size_t)((wn*64 + g) * 128);

    for (int t = 0; t < LL; t++){
        const char* Ah = sm + ((t & 1) ? SM_A1H : SM_A0H);
        const char* Al = Ah + 8192;
        char* AwH = sm + ((t & 1) ? SM_A0H : SM_A1H);
        char* AwL = AwH + 8192;
        const char* ArH = Ah + mt*2048 + g*128;
        const char* ArL = Al + mt*2048 + g*128;

        float acc[32];
        #pragma unroll
        for (int i = 0; i < 32; i++) acc[i] = 0.f;

        #pragma unroll
        for (int K0 = 0; K0 < 64; K0 += 16){
            u32 o0 = ((u32)(2*K0 + 4*tq)) ^ xorv;
            u32 o8 = o0 ^ 16u;
            u32 ah[4], al[4];
            ah[0] = *(const u32*)(ArH +        o0);
            ah[1] = *(const u32*)(ArH + 1024 + o0);
            ah[2] = *(const u32*)(ArH +        o8);
            ah[3] = *(const u32*)(ArH + 1024 + o8);
            al[0] = *(const u32*)(ArL +        o0);
            al[1] = *(const u32*)(ArL + 1024 + o0);
            al[2] = *(const u32*)(ArL +        o8);
            al[3] = *(const u32*)(ArL + 1024 + o8);
            #pragma unroll
            for (int j = 0; j < 8; j++){
                u32 bh[2], bl[2];
                bh[0] = *(const u32*)(Bh0 + j*1024 + o0);
                bh[1] = *(const u32*)(Bh0 + j*1024 + o8);
                bl[0] = *(const u32*)(Bl0 + j*1024 + o0);
                bl[1] = *(const u32*)(Bl0 + j*1024 + o8);
                mma_bf16(acc + j*4, ah, bh);
                mma_bf16(acc + j*4, ah, bl);
                mma_bf16(acc + j*4, al, bh);
            }
        }

        // ---- epilogue: gates -> (c,h), write h bf16 hi/lo ----
        float xv0 = sXf[(mt*16 + g    )*129 + t];
        float xv1 = sXf[(mt*16 + g + 8)*129 + t];
        #pragma unroll
        for (int dlh = 0; dlh < 2; dlh++){
            int nI = wn*64 + dlh*8 + 2*tq;
            float2 aI = *(const float2*)(sCa + nI     );
            float2 aF = *(const float2*)(sCa + nI + 16);
            float2 aG = *(const float2*)(sCa + nI + 32);
            float2 aO = *(const float2*)(sCa + nI + 48);
            float2 cI = *(const float2*)(sCb + nI     );
            float2 cF = *(const float2*)(sCb + nI + 16);
            float2 cG = *(const float2*)(sCb + nI + 32);
            float2 cO = *(const float2*)(sCb + nI + 48);
            #pragma unroll
            for (int s = 0; s < 2; s++){
                float xv = s ? xv1 : xv0;
                float h2[2];
                #pragma unroll
                for (int u = 0; u < 2; u++){
                    int fi = s*2 + u;
                    float gi = acc[(dlh    )*4 + fi] + (u?aI.y:aI.x)*xv + (u?cI.y:cI.x);
                    float gf = acc[(2+dlh  )*4 + fi] + (u?aF.y:aF.x)*xv + (u?cF.y:cF.x);
                    float gg = acc[(4+dlh  )*4 + fi] + (u?aG.y:aG.x)*xv + (u?cG.y:cG.x);
                    float go = acc[(6+dlh  )*4 + fi] + (u?aO.y:aO.x)*xv + (u?cO.y:cO.x);
                    int ci = dlh*4 + fi;
                    float c2 = sigf(gf)*creg[ci] + sigf(gi)*tanhp(gg);
                    creg[ci] = c2;
                    h2[u] = sigf(go)*tanhp(c2);
                }
                __nv_bfloat16 b0 = __float2bfloat16(h2[0]);
                __nv_bfloat16 b1 = __float2bfloat16(h2[1]);
                u32 hp = (u32)__bfloat16_as_ushort(b0) | ((u32)__bfloat16_as_ushort(b1) << 16);
                __nv_bfloat16 l0 = __float2bfloat16(h2[0] - __bfloat162float(b0));
                __nv_bfloat16 l1 = __float2bfloat16(h2[1] - __bfloat162float(b1));
                u32 lp = (u32)__bfloat16_as_ushort(l0) | ((u32)__bfloat16_as_ushort(l1) << 16);
                int r = mt*16 + g + s*8;
                u32 cbS = ((u32)(wn*32 + dlh*16 + 4*tq)) ^ xorv;
                *(u32*)(AwH + r*128 + cbS) = hp;
                *(u32*)(AwL + r*128 + cbS) = lp;
            }
        }
        __syncthreads();
    }

    // ---- final per-CTA stage ----
    float* sHfin = (float*)(sm + SM_X);            // [row][d] stride 64
    float* sCst  = (float*)(sm + SM_X + 16384);
    #pragma unroll
    for (int dlh = 0; dlh < 2; dlh++){
        #pragma unroll
        for (int s = 0; s < 2; s++){
            #pragma unroll
            for (int u = 0; u < 2; u++){
                int r  = mt*16 + g + s*8;
                int d  = wn*16 + dlh*8 + 2*tq + u;
                u32 sw = ((u32)(2*d)) ^ xorv;
                float h = __bfloat162float(*(const __nv_bfloat16*)(sm + SM_A0H + r*128 + sw))
                        + __bfloat162float(*(const __nv_bfloat16*)(sm + SM_A0L + r*128 + sw));
                sHfin[r*64 + d] = h;
                sCst [r*64 + d] = creg[dlh*4 + s*2 + u];
            }
        }
    }
    float* sWa = (float*)(sm + SM_BH);
    float* sWf = sWa + 4096;
    for (int i = tid; i < 4096; i += NTHR){ sWa[i] = W_aout[i]; sWf[i] = W_fh[i]; }
    __syncthreads();

    float* sHhat = (float*)(sm + SM_A0H);          // [row][d] stride 64 (16KB)
    const int row = tid >> 3;
    const int d0  = (tid & 7) << 3;
    #pragma unroll 2
    for (int jj = 0; jj < 8; jj++){
        int d = d0 + jj;
        float acc2 = __ldg(b_aout + d);
        #pragma unroll 8
        for (int e = 0; e < DD; e++) acc2 += sHfin[row*64 + e] * sWa[d*64 + e];
        sHhat[row*64 + d] = acc2;
        atomicAdd(&sRd[64 + d], acc2);
    }
    __syncthreads();
    #pragma unroll 2
    for (int jj = 0; jj < 8; jj++){
        int d = d0 + jj;
        float f = __ldg(b_fh + d);
        #pragma unroll 8
        for (int e = 0; e < DD; e++) f += sHhat[row*64 + e] * sWf[d*64 + e];
        atomicAdd(&sRd[d], sigf(f) * sCst[row*64 + d]);
    }
    __syncthreads();
    if (tid < 128) atomicAdd(&g_acc[tid], sRd[tid]);
}

// ---------- finisher ----------
__global__ void fin_kernel(const float* __restrict__ W_iouh, const float* __restrict__ b_iouh,
                           const float* __restrict__ W_oout, const float* __restrict__ b_oout,
                           float* __restrict__ out){
    __shared__ float sfc[64], shs[64], sho[64];
    int d = threadIdx.x;   // 0..63
    sfc[d] = g_acc[d];
    shs[d] = g_acc[64 + d];
    __syncthreads();
    float vi = b_iouh[d], vo = b_iouh[64 + d], vu = b_iouh[128 + d];
    #pragma unroll 8
    for (int e = 0; e < DD; e++){
        float h = shs[e];
        vi += h * W_iouh[(      d)*64 + e];
        vo += h * W_iouh[( 64 + d)*64 + e];
        vu += h * W_iouh[(128 + d)*64 + e];
    }
    float cobj = sigf(vi)*tanhp(vu) + sfc[d];
    sho[d] = sigf(vo)*tanhp(cobj);
    __syncthreads();
    float acc = b_oout[d];
    #pragma unroll 8
    for (int e = 0; e < DD; e++) acc += sho[e] * W_oout[d*64 + e];
    out[d]      = acc;
    out[64 + d] = cobj;
}

extern "C" void kernel_launch(void* const* d_in, const int* in_sizes, int n_in,
                              void* d_out, int out_size){
    const float* x      = (const float*)d_in[0];
    const float* W_num  = (const float*)d_in[1];
    const float* b_num  = (const float*)d_in[2];
    const float* W_ih   = (const float*)d_in[3];
    const float* W_hh   = (const float*)d_in[4];
    const float* b_ih   = (const float*)d_in[5];
    const float* b_hh   = (const float*)d_in[6];
    const float* W_aout = (const float*)d_in[7];
    const float* b_aout = (const float*)d_in[8];
    const float* W_fh   = (const float*)d_in[9];
    const float* b_fh   = (const float*)d_in[10];
    const float* W_iouh = (const float*)d_in[11];
    const float* b_iouh = (const float*)d_in[12];
    const float* W_oout = (const float*)d_in[13];
    const float* b_oout = (const float*)d_in[14];
    float* out = (float*)d_out;

    cudaFuncSetAttribute(lstm_kernel, cudaFuncAttributeMaxDynamicSharedMemorySize, SM_TOT);

    prep_kernel<<<1, 256>>>(W_ih, W_num, b_num, b_ih, b_hh, W_hh);
    lstm_kernel<<<NBLK, NTHR, SM_TOT>>>(x, W_aout, b_aout, W_fh, b_fh);
    fin_kernel<<<1, 64>>>(W_iouh, b_iouh, W_oout, b_oout, out);
}

// round 8
// speedup vs baseline: 1.3010x; 1.3010x over previous
#include <cuda_runtime.h>
#include <cuda_fp16.h>
#include <cstdint>

#define DD 64
#define LL 128
#define KROWS 8192
#define MROWS 64
#define NBLK (KROWS/MROWS)   // 128 CTAs
#define NTHR 256

typedef unsigned int u32;

// smem byte offsets
#define SM_A0H 0          // h buf0 hi: 64 rows x 128B (fp16)
#define SM_A0L 8192
#define SM_A1H 16384
#define SM_A1L 24576
#define SM_BH  32768      // W fp16: 256 n-rows x 128B
#define SM_X   65536      // x: 64 x 129 floats = 33024B
#define SM_CA  98560      // 256 floats
#define SM_CB  99584      // 256 floats
#define SM_RED 100608     // 128 floats
#define SM_FIN 101120     // 3*64 floats fin scratch
#define SM_FLG 101888     // 4B last-CTA flag
#define SM_TOT 101952

__device__ float g_acc[128];          // zero-initialized at module load; reset by last CTA
__device__ unsigned int g_ctr = 0;

__device__ __forceinline__ float fexp(float x){
    x = fmaxf(fminf(x, 30.f), -30.f);
    return __expf(x);
}
__device__ __forceinline__ float sigf(float x){
    return __fdividef(1.0f, 1.0f + fexp(-x));
}
__device__ __forceinline__ float tanhp(float x){
    return 2.0f * __fdividef(1.0f, 1.0f + fexp(-2.0f*x)) - 1.0f;
}

__device__ __forceinline__ void mma_fp16(float* c, const u32* a, const u32* b){
    asm volatile("mma.sync.aligned.m16n8k16.row.col.f32.f16.f16.f32 "
        "{%0,%1,%2,%3}, {%4,%5,%6,%7}, {%8,%9}, {%0,%1,%2,%3};\n"
        : "+f"(c[0]),"+f"(c[1]),"+f"(c[2]),"+f"(c[3])
        : "r"(a[0]),"r"(a[1]),"r"(a[2]),"r"(a[3]), "r"(b[0]),"r"(b[1]));
}

// ---------- single fused kernel ----------
__global__ void __launch_bounds__(NTHR,1)
lstm_kernel(const float* __restrict__ x,
            const float* __restrict__ W_num,  const float* __restrict__ b_num,
            const float* __restrict__ W_ih,   const float* __restrict__ W_hh,
            const float* __restrict__ b_ih,   const float* __restrict__ b_hh,
            const float* __restrict__ W_aout, const float* __restrict__ b_aout,
            const float* __restrict__ W_fh,   const float* __restrict__ b_fh,
            const float* __restrict__ W_iouh, const float* __restrict__ b_iouh,
            const float* __restrict__ W_oout, const float* __restrict__ b_oout,
            float* __restrict__ out){
    extern __shared__ char sm[];
    const int tid  = threadIdx.x;
    const int wid  = tid >> 5;
    const int lane = tid & 31;
    const int g    = lane >> 2;      // group 0..7
    const int tq   = lane & 3;       // quad  0..3
    const int mt   = wid & 3;        // m-tile 0..3 (rows mt*16..)
    const int wn   = wid >> 2;       // n-half 0/1
    const u32 xorv = (u32)g << 4;
    const int r0   = blockIdx.x * MROWS;

    float* sXf = (float*)(sm + SM_X);
    float* sCa = (float*)(sm + SM_CA);
    float* sCb = (float*)(sm + SM_CB);
    float* sRd = (float*)(sm + SM_RED);

    // ---- per-CTA prep: consts + fp16 W tile (reordered + swizzled) ----
    // Column order: n = wn2*128 + j*8 + c; gate G = j>>2; dl=(j&3)*8+c; d = wn2*32+dl.
    {
        int n = tid;                // 0..255
        int wn2 = n >> 7;
        int rem = n & 127;
        int j = rem >> 3;
        int c = rem & 7;
        int G = j >> 2;
        int dl = (j & 3)*8 + c;
        int d  = wn2*32 + dl;
        int wr = G*64 + d;
        float sa = 0.f, sc = 0.f;
        #pragma unroll 8
        for (int k = 0; k < DD; k++){
            float w = __ldg(W_ih + wr*(2*DD) + k);
            sa += w * __ldg(W_num + k);
            sc += w * __ldg(b_num + k);
        }
        sCa[n] = sa;
        sCb[n] = sc + __ldg(b_ih + wr) + __ldg(b_hh + wr);
        #pragma unroll 8
        for (int k = 0; k < DD; k++){
            float w = __ldg(W_hh + wr*DD + k);
            u32 off = (u32)n*128 + (u32)k*2;
            u32 sw  = off ^ (((u32)n & 7u) << 4);
            *(__half*)(sm + SM_BH + sw) = __float2half_rn(w);
        }
        uint4 z = make_uint4(0,0,0,0);
        uint4* da = (uint4*)(sm + SM_A0H);
        for (int i = tid; i < 2048; i += NTHR) da[i] = z;   // all 4 A buffers (32KB)
        for (int idx = tid; idx < MROWS*LL; idx += NTHR){
            int rr = idx >> 7, tt = idx & 127;
            sXf[rr*129 + tt] = x[(size_t)(r0 + rr)*LL + tt];
        }
        if (tid < 128) sRd[tid] = 0.f;
    }
    __syncthreads();

    float creg[16];
    #pragma unroll
    for (int i = 0; i < 16; i++) creg[i] = 0.f;

    const char* Bh0 = sm + SM_BH + (size_t)((wn*128 + g) * 128);

    for (int t = 0; t < LL; t++){
        const char* Ah = sm + ((t & 1) ? SM_A1H : SM_A0H);
        const char* Al = Ah + 8192;
        char* AwH = sm + ((t & 1) ? SM_A0H : SM_A1H);
        char* AwL = AwH + 8192;
        const char* ArH = Ah + mt*2048 + g*128;
        const char* ArL = Al + mt*2048 + g*128;

        float acc[64];
        #pragma unroll
        for (int i = 0; i < 64; i++) acc[i] = 0.f;

        #pragma unroll
        for (int K0 = 0; K0 < 64; K0 += 16){
            u32 o0 = ((u32)(2*K0 + 4*tq)) ^ xorv;
            u32 o8 = o0 ^ 16u;
            u32 ah[4], al[4];
            ah[0] = *(const u32*)(ArH +        o0);
            ah[1] = *(const u32*)(ArH + 1024 + o0);
            ah[2] = *(const u32*)(ArH +        o8);
            ah[3] = *(const u32*)(ArH + 1024 + o8);
            al[0] = *(const u32*)(ArL +        o0);
            al[1] = *(const u32*)(ArL + 1024 + o0);
            al[2] = *(const u32*)(ArL +        o8);
            al[3] = *(const u32*)(ArL + 1024 + o8);
            #pragma unroll
            for (int j = 0; j < 16; j++){
                u32 bh[2];
                bh[0] = *(const u32*)(Bh0 + j*1024 + o0);
                bh[1] = *(const u32*)(Bh0 + j*1024 + o8);
                mma_fp16(acc + j*4, ah, bh);
                mma_fp16(acc + j*4, al, bh);
            }
        }

        // ---- epilogue: gates -> (c,h), write h fp16 hi/lo ----
        float xv0 = sXf[(mt*16 + g    )*129 + t];
        float xv1 = sXf[(mt*16 + g + 8)*129 + t];
        #pragma unroll
        for (int q = 0; q < 4; q++){
            int nI = wn*128 + q*8 + 2*tq;
            float2 aI = *(const float2*)(sCa + nI     );
            float2 aF = *(const float2*)(sCa + nI + 32);
            float2 aG = *(const float2*)(sCa + nI + 64);
            float2 aO = *(const float2*)(sCa + nI + 96);
            float2 cI = *(const float2*)(sCb + nI     );
            float2 cF = *(const float2*)(sCb + nI + 32);
            float2 cG = *(const float2*)(sCb + nI + 64);
            float2 cO = *(const float2*)(sCb + nI + 96);
            #pragma unroll
            for (int s = 0; s < 2; s++){
                float xv = s ? xv1 : xv0;
                float h2[2];
                #pragma unroll
                for (int u = 0; u < 2; u++){
                    int fi = s*2 + u;
                    float gi = acc[( q    )*4 + fi] + (u?aI.y:aI.x)*xv + (u?cI.y:cI.x);
                    float gf = acc[( 4+q  )*4 + fi] + (u?aF.y:aF.x)*xv + (u?cF.y:cF.x);
                    float gg = acc[( 8+q  )*4 + fi] + (u?aG.y:aG.x)*xv + (u?cG.y:cG.x);
                    float go = acc[(12+q  )*4 + fi] + (u?aO.y:aO.x)*xv + (u?cO.y:cO.x);
                    int ci = q*4 + fi;
                    float c2 = sigf(gf)*creg[ci] + sigf(gi)*tanhp(gg);
                    creg[ci] = c2;
                    h2[u] = sigf(go)*tanhp(c2);
                }
                __half b0 = __float2half_rn(h2[0]);
                __half b1 = __float2half_rn(h2[1]);
                u32 hp = (u32)__half_as_ushort(b0) | ((u32)__half_as_ushort(b1) << 16);
                __half l0 = __float2half_rn(h2[0] - __half2float(b0));
                __half l1 = __float2half_rn(h2[1] - __half2float(b1));
                u32 lp = (u32)__half_as_ushort(l0) | ((u32)__half_as_ushort(l1) << 16);
                int r = mt*16 + g + s*8;
                u32 cbS = ((u32)(wn*64 + q*16 + 4*tq)) ^ xorv;
                *(u32*)(AwH + r*128 + cbS) = hp;
                *(u32*)(AwL + r*128 + cbS) = lp;
            }
        }
        __syncthreads();
    }

    // ---- final per-CTA stage ----
    float* sHfin = (float*)(sm + SM_X);            // [row][d] stride 64
    float* sCst  = (float*)(sm + SM_X + 16384);
    #pragma unroll
    for (int q = 0; q < 4; q++){
        #pragma unroll
        for (int s = 0; s < 2; s++){
            #pragma unroll
            for (int u = 0; u < 2; u++){
                int r  = mt*16 + g + s*8;
                int dl = q*8 + 2*tq + u;
                int d  = wn*32 + dl;
                u32 sw = ((u32)(2*d)) ^ xorv;
                float h = __half2float(*(const __half*)(sm + SM_A0H + r*128 + sw))
                        + __half2float(*(const __half*)(sm + SM_A0L + r*128 + sw));
                sHfin[r*64 + d] = h;
                sCst [r*64 + d] = creg[q*4 + s*2 + u];
            }
        }
    }
    // stage W_aout / W_fh over the BH region (32KB exactly)
    float* sWa = (float*)(sm + SM_BH);
    float* sWf = sWa + 4096;
    for (int i = tid; i < 4096; i += NTHR){ sWa[i] = W_aout[i]; sWf[i] = W_fh[i]; }
    __syncthreads();

    float* sHhat = (float*)(sm + SM_A0H);          // [row][d] stride 64 (16KB)
    const int row = tid >> 2;
    const int d0  = (tid & 3) << 4;
    #pragma unroll 2
    for (int jj = 0; jj < 16; jj++){
        int d = d0 + jj;
        float acc2 = __ldg(b_aout + d);
        #pragma unroll 8
        for (int e = 0; e < DD; e++) acc2 += sHfin[row*64 + e] * sWa[d*64 + e];
        sHhat[row*64 + d] = acc2;
        atomicAdd(&sRd[64 + d], acc2);
    }
    __syncthreads();
    #pragma unroll 2
    for (int jj = 0; jj < 16; jj++){
        int d = d0 + jj;
        float f = __ldg(b_fh + d);
        #pragma unroll 8
        for (int e = 0; e < DD; e++) f += sHhat[row*64 + e] * sWf[d*64 + e];
        atomicAdd(&sRd[d], sigf(f) * sCst[row*64 + d]);
    }
    __syncthreads();

    // ---- global reduction + last-CTA finisher ----
    if (tid < 128) atomicAdd(&g_acc[tid], sRd[tid]);
    __threadfence();
    __syncthreads();
    if (tid == 0){
        unsigned int rnk = atomicAdd(&g_ctr, 1);
        *(u32*)(sm + SM_FLG) = (rnk == NBLK - 1) ? 1u : 0u;
    }
    __syncthreads();
    if (*(const u32*)(sm + SM_FLG)){
        float* sfc = (float*)(sm + SM_FIN);
        float* shs = sfc + 64;
        float* sho = sfc + 128;
        if (tid < 64){ sfc[tid] = g_acc[tid]; shs[tid] = g_acc[64 + tid]; }
        __syncthreads();
        if (tid < 64){
            int d = tid;
            float vi = __ldg(b_iouh + d), vo = __ldg(b_iouh + 64 + d), vu = __ldg(b_iouh + 128 + d);
            #pragma unroll 8
            for (int e = 0; e < DD; e++){
                float h = shs[e];
                vi += h * __ldg(W_iouh + (      d)*64 + e);
                vo += h * __ldg(W_iouh + ( 64 + d)*64 + e);
                vu += h * __ldg(W_iouh + (128 + d)*64 + e);
            }
            float cobj = sigf(vi)*tanhp(vu) + sfc[d];
            sho[d] = sigf(vo)*tanhp(cobj);
            out[64 + d] = cobj;
        }
        __syncthreads();
        if (tid < 64){
            int d = tid;
            float acc3 = __ldg(b_oout + d);
            #pragma unroll 8
            for (int e = 0; e < DD; e++) acc3 += sho[e] * __ldg(W_oout + d*64 + e);
            out[d] = acc3;
        }
        // reset accumulators for the next graph replay
        if (tid < 128) g_acc[tid] = 0.f;
        __threadfence();
        if (tid == 0) g_ctr = 0;
    }
}

extern "C" void kernel_launch(void* const* d_in, const int* in_sizes, int n_in,
                              void* d_out, int out_size){
    const float* x      = (const float*)d_in[0];
    const float* W_num  = (const float*)d_in[1];
    const float* b_num  = (const float*)d_in[2];
    const float* W_ih   = (const float*)d_in[3];
    const float* W_hh   = (const float*)d_in[4];
    const float* b_ih   = (const float*)d_in[5];
    const float* b_hh   = (const float*)d_in[6];
    const float* W_aout = (const float*)d_in[7];
    const float* b_aout = (const float*)d_in[8];
    const float* W_fh   = (const float*)d_in[9];
    const float* b_fh   = (const float*)d_in[10];
    const float* W_iouh = (const float*)d_in[11];
    const float* b_iouh = (const float*)d_in[12];
    const float* W_oout = (const float*)d_in[13];
    const float* b_oout = (const float*)d_in[14];
    float* out = (float*)d_out;

    cudaFuncSetAttribute(lstm_kernel, cudaFuncAttributeMaxDynamicSharedMemorySize, SM_TOT);

    lstm_kernel<<<NBLK, NTHR, SM_TOT>>>(x, W_num, b_num, W_ih, W_hh, b_ih, b_hh,
                                        W_aout, b_aout, W_fh, b_fh,
                                        W_iouh, b_iouh, W_oout, b_oout, out);
}

// round 9
// speedup vs baseline: 1.8129x; 1.3935x over previous
#include <cuda_runtime.h>
#include <cuda_fp16.h>
#include <cstdint>

#define DD 64
#define LL 128
#define KROWS 8192
#define MROWS 64
#define NBLK (KROWS/MROWS)   // 128 CTAs
#define NTHR 256

typedef unsigned int u32;

// smem byte offsets
#define SM_A0  0          // h buf0: 64 rows x 128B (fp16)
#define SM_A1  8192
#define SM_BH  16384      // W fp16: 256 n-rows x 128B (32KB)
#define SM_X   49152      // x: 64 x 129 floats = 33024B
#define SM_CA  82176      // 256 floats
#define SM_CB  83200      // 256 floats
#define SM_RED 84224      // 128 floats
#define SM_FIN 84736      // 3*64 floats
#define SM_FLG 85504      // 4B
#define SM_TOT 85568

__device__ float g_acc[128];          // zeroed at load; reset by last CTA each run
__device__ unsigned int g_ctr = 0;

__device__ __forceinline__ float fexp(float x){
    x = fmaxf(fminf(x, 30.f), -30.f);
    return __expf(x);
}
__device__ __forceinline__ float sigf(float x){
    return __fdividef(1.0f, 1.0f + fexp(-x));
}
__device__ __forceinline__ float tanhp(float x){
    return 2.0f * __fdividef(1.0f, 1.0f + fexp(-2.0f*x)) - 1.0f;
}
// fast path (recurrent loop only)
__device__ __forceinline__ float tanha(float x){
    float r; asm("tanh.approx.f32 %0, %1;" : "=f"(r) : "f"(x)); return r;
}
__device__ __forceinline__ float siga(float x){
    return fmaf(0.5f, tanha(0.5f*x), 0.5f);
}

__device__ __forceinline__ void mma_fp16(float* c, const u32* a, const u32* b){
    asm volatile("mma.sync.aligned.m16n8k16.row.col.f32.f16.f16.f32 "
        "{%0,%1,%2,%3}, {%4,%5,%6,%7}, {%8,%9}, {%0,%1,%2,%3};\n"
        : "+f"(c[0]),"+f"(c[1]),"+f"(c[2]),"+f"(c[3])
        : "r"(a[0]),"r"(a[1]),"r"(a[2]),"r"(a[3]), "r"(b[0]),"r"(b[1]));
}

// ---------- single fused kernel ----------
__global__ void __launch_bounds__(NTHR,1)
lstm_kernel(const float* __restrict__ x,
            const float* __restrict__ W_num,  const float* __restrict__ b_num,
            const float* __restrict__ W_ih,   const float* __restrict__ W_hh,
            const float* __restrict__ b_ih,   const float* __restrict__ b_hh,
            const float* __restrict__ W_aout, const float* __restrict__ b_aout,
            const float* __restrict__ W_fh,   const float* __restrict__ b_fh,
            const float* __restrict__ W_iouh, const float* __restrict__ b_iouh,
            const float* __restrict__ W_oout, const float* __restrict__ b_oout,
            float* __restrict__ out){
    extern __shared__ char sm[];
    const int tid  = threadIdx.x;
    const int wid  = tid >> 5;
    const int lane = tid & 31;
    const int g    = lane >> 2;      // group 0..7
    const int tq   = lane & 3;       // quad  0..3
    const int mt   = wid & 3;        // m-tile 0..3 (rows mt*16..)
    const int wn   = wid >> 2;       // n-half 0/1
    const u32 xorv = (u32)g << 4;
    const int r0   = blockIdx.x * MROWS;

    float* sXf = (float*)(sm + SM_X);
    float* sCa = (float*)(sm + SM_CA);
    float* sCb = (float*)(sm + SM_CB);
    float* sRd = (float*)(sm + SM_RED);

    // ---- per-CTA prep: consts + fp16 W tile (reordered + swizzled) ----
    // Column order: n = wn2*128 + j*8 + c; gate G = j>>2; dl=(j&3)*8+c; d = wn2*32+dl.
    {
        int n = tid;                // 0..255
        int wn2 = n >> 7;
        int rem = n & 127;
        int j = rem >> 3;
        int c = rem & 7;
        int G = j >> 2;
        int dl = (j & 3)*8 + c;
        int d  = wn2*32 + dl;
        int wr = G*64 + d;
        float sa = 0.f, sc = 0.f;
        #pragma unroll 8
        for (int k = 0; k < DD; k++){
            float w = __ldg(W_ih + wr*(2*DD) + k);
            sa += w * __ldg(W_num + k);
            sc += w * __ldg(b_num + k);
        }
        sCa[n] = sa;
        sCb[n] = sc + __ldg(b_ih + wr) + __ldg(b_hh + wr);
        #pragma unroll 8
        for (int k = 0; k < DD; k++){
            float w = __ldg(W_hh + wr*DD + k);
            u32 off = (u32)n*128 + (u32)k*2;
            u32 sw  = off ^ (((u32)n & 7u) << 4);
            *(__half*)(sm + SM_BH + sw) = __float2half_rn(w);
        }
        uint4 z = make_uint4(0,0,0,0);
        uint4* da = (uint4*)(sm + SM_A0);
        for (int i = tid; i < 1024; i += NTHR) da[i] = z;   // A0+A1 (16KB)
        for (int idx = tid; idx < MROWS*LL; idx += NTHR){
            int rr = idx >> 7, tt = idx & 127;
            sXf[rr*129 + tt] = x[(size_t)(r0 + rr)*LL + tt];
        }
        if (tid < 128) sRd[tid] = 0.f;
    }
    __syncthreads();

    float creg[16];
    #pragma unroll
    for (int i = 0; i < 16; i++) creg[i] = 0.f;

    const char* Bh0 = sm + SM_BH + (size_t)((wn*128 + g) * 128);

    for (int t = 0; t < LL; t++){
        const char* Ah = sm + ((t & 1) ? SM_A1 : SM_A0);
        char* Aw = sm + ((t & 1) ? SM_A0 : SM_A1);
        const char* ArH = Ah + mt*2048 + g*128;

        float acc[64];
        #pragma unroll
        for (int i = 0; i < 64; i++) acc[i] = 0.f;

        #pragma unroll
        for (int K0 = 0; K0 < 64; K0 += 16){
            u32 o0 = ((u32)(2*K0 + 4*tq)) ^ xorv;
            u32 o8 = o0 ^ 16u;
            u32 ah[4];
            ah[0] = *(const u32*)(ArH +        o0);
            ah[1] = *(const u32*)(ArH + 1024 + o0);
            ah[2] = *(const u32*)(ArH +        o8);
            ah[3] = *(const u32*)(ArH + 1024 + o8);
            #pragma unroll
            for (int j = 0; j < 16; j++){
                u32 bh[2];
                bh[0] = *(const u32*)(Bh0 + j*1024 + o0);
                bh[1] = *(const u32*)(Bh0 + j*1024 + o8);
                mma_fp16(acc + j*4, ah, bh);
            }
        }

        // ---- epilogue: gates -> (c,h), write h fp16 ----
        float xv0 = sXf[(mt*16 + g    )*129 + t];
        float xv1 = sXf[(mt*16 + g + 8)*129 + t];
        #pragma unroll
        for (int q = 0; q < 4; q++){
            int nI = wn*128 + q*8 + 2*tq;
            float2 aI = *(const float2*)(sCa + nI     );
            float2 aF = *(const float2*)(sCa + nI + 32);
            float2 aG = *(const float2*)(sCa + nI + 64);
            float2 aO = *(const float2*)(sCa + nI + 96);
            float2 cI = *(const float2*)(sCb + nI     );
            float2 cF = *(const float2*)(sCb + nI + 32);
            float2 cG = *(const float2*)(sCb + nI + 64);
            float2 cO = *(const float2*)(sCb + nI + 96);
            #pragma unroll
            for (int s = 0; s < 2; s++){
                float xv = s ? xv1 : xv0;
                float h2[2];
                #pragma unroll
                for (int u = 0; u < 2; u++){
                    int fi = s*2 + u;
                    float gi = acc[( q    )*4 + fi] + (u?aI.y:aI.x)*xv + (u?cI.y:cI.x);
                    float gf = acc[( 4+q  )*4 + fi] + (u?aF.y:aF.x)*xv + (u?cF.y:cF.x);
                    float gg = acc[( 8+q  )*4 + fi] + (u?aG.y:aG.x)*xv + (u?cG.y:cG.x);
                    float go = acc[(12+q  )*4 + fi] + (u?aO.y:aO.x)*xv + (u?cO.y:cO.x);
                    int ci = q*4 + fi;
                    float c2 = siga(gf)*creg[ci] + siga(gi)*tanha(gg);
                    creg[ci] = c2;
                    h2[u] = siga(go)*tanha(c2);
                }
                __half b0 = __float2half_rn(h2[0]);
                __half b1 = __float2half_rn(h2[1]);
                u32 hp = (u32)__half_as_ushort(b0) | ((u32)__half_as_ushort(b1) << 16);
                int r = mt*16 + g + s*8;
                u32 cbS = ((u32)(wn*64 + q*16 + 4*tq)) ^ xorv;
                *(u32*)(Aw + r*128 + cbS) = hp;
            }
        }
        __syncthreads();
    }

    // ---- final per-CTA stage ----
    float* sHfin = (float*)(sm + SM_X);            // [row][d] stride 64
    float* sCst  = (float*)(sm + SM_X + 16384);
    #pragma unroll
    for (int q = 0; q < 4; q++){
        #pragma unroll
        for (int s = 0; s < 2; s++){
            #pragma unroll
            for (int u = 0; u < 2; u++){
                int r  = mt*16 + g + s*8;
                int dl = q*8 + 2*tq + u;
                int d  = wn*32 + dl;
                u32 sw = ((u32)(2*d)) ^ xorv;
                float h = __half2float(*(const __half*)(sm + SM_A0 + r*128 + sw));
                sHfin[r*64 + d] = h;
                sCst [r*64 + d] = creg[q*4 + s*2 + u];
            }
        }
    }
    // stage W_aout / W_fh over the BH region (32KB exactly)
    float* sWa = (float*)(sm + SM_BH);
    float* sWf = sWa + 4096;
    for (int i = tid; i < 4096; i += NTHR){ sWa[i] = W_aout[i]; sWf[i] = W_fh[i]; }
    __syncthreads();

    float* sHhat = (float*)(sm + SM_A0);           // [row][d] stride 64 (16KB = A0+A1)
    const int row = tid >> 2;
    const int d0  = (tid & 3) << 4;
    #pragma unroll 2
    for (int jj = 0; jj < 16; jj++){
        int d = d0 + jj;
        float acc2 = __ldg(b_aout + d);
        #pragma unroll 8
        for (int e = 0; e < DD; e++) acc2 += sHfin[row*64 + e] * sWa[d*64 + e];
        sHhat[row*64 + d] = acc2;
        atomicAdd(&sRd[64 + d], acc2);
    }
    __syncthreads();
    #pragma unroll 2
    for (int jj = 0; jj < 16; jj++){
        int d = d0 + jj;
        float f = __ldg(b_fh + d);
        #pragma unroll 8
        for (int e = 0; e < DD; e++) f += sHhat[row*64 + e] * sWf[d*64 + e];
        atomicAdd(&sRd[d], sigf(f) * sCst[row*64 + d]);
    }
    __syncthreads();

    // ---- global reduction + last-CTA finisher ----
    if (tid < 128) atomicAdd(&g_acc[tid], sRd[tid]);
    __threadfence();
    __syncthreads();
    if (tid == 0){
        unsigned int rnk = atomicAdd(&g_ctr, 1);
        *(u32*)(sm + SM_FLG) = (rnk == NBLK - 1) ? 1u : 0u;
    }
    __syncthreads();
    if (*(const u32*)(sm + SM_FLG)){
        float* sfc = (float*)(sm + SM_FIN);
        float* shs = sfc + 64;
        float* sho = sfc + 128;
        if (tid < 64){ sfc[tid] = g_acc[tid]; shs[tid] = g_acc[64 + tid]; }
        __syncthreads();
        if (tid < 64){
            int d = tid;
            float vi = __ldg(b_iouh + d), vo = __ldg(b_iouh + 64 + d), vu = __ldg(b_iouh + 128 + d);
            #pragma unroll 8
            for (int e = 0; e < DD; e++){
                float h = shs[e];
                vi += h * __ldg(W_iouh + (      d)*64 + e);
                vo += h * __ldg(W_iouh + ( 64 + d)*64 + e);
                vu += h * __ldg(W_iouh + (128 + d)*64 + e);
            }
            float cobj = sigf(vi)*tanhp(vu) + sfc[d];
            sho[d] = sigf(vo)*tanhp(cobj);
            out[64 + d] = cobj;
        }
        __syncthreads();
        if (tid < 64){
            int d = tid;
            float acc3 = __ldg(b_oout + d);
            #pragma unroll 8
            for (int e = 0; e < DD; e++) acc3 += sho[e] * __ldg(W_oout + d*64 + e);
            out[d] = acc3;
        }
        // reset accumulators for the next graph replay
        if (tid < 128) g_acc[tid] = 0.f;
        __threadfence();
        if (tid == 0) g_ctr = 0;
    }
}

extern "C" void kernel_launch(void* const* d_in, const int* in_sizes, int n_in,
                              void* d_out, int out_size){
    const float* x      = (const float*)d_in[0];
    const float* W_num  = (const float*)d_in[1];
    const float* b_num  = (const float*)d_in[2];
    const float* W_ih   = (const float*)d_in[3];
    const float* W_hh   = (const float*)d_in[4];
    const float* b_ih   = (const float*)d_in[5];
    const float* b_hh   = (const float*)d_in[6];
    const float* W_aout = (const float*)d_in[7];
    const float* b_aout = (const float*)d_in[8];
    const float* W_fh   = (const float*)d_in[9];
    const float* b_fh   = (const float*)d_in[10];
    const float* W_iouh = (const float*)d_in[11];
    const float* b_iouh = (const float*)d_in[12];
    const float* W_oout = (const float*)d_in[13];
    const float* b_oout = (const float*)d_in[14];
    float* out = (float*)d_out;

    cudaFuncSetAttribute(lstm_kernel, cudaFuncAttributeMaxDynamicSharedMemorySize, SM_TOT);

    lstm_kernel<<<NBLK, NTHR, SM_TOT>>>(x, W_num, b_num, W_ih, W_hh, b_ih, b_hh,
                                        W_aout, b_aout, W_fh, b_fh,
                                        W_iouh, b_iouh, W_oout, b_oout, out);
}

// round 10
// speedup vs baseline: 1.8455x; 1.0180x over previous
#include <cuda_runtime.h>
#include <cuda_fp16.h>
#include <cstdint>

#define DD 64
#define LL 128
#define KROWS 8192
#define MROWS 64
#define NBLK (KROWS/MROWS)   // 128 CTAs
#define NTHR 512

typedef unsigned int u32;

// smem byte offsets
#define SM_A0  0          // h buf0: 64 rows x 128B (fp16)
#define SM_A1  8192
#define SM_BH  16384      // W fp16 staging: 256 n-rows x 128B (32KB); reused for sWa/sWf
#define SM_X   49152      // x: 64 x 129 floats = 33024B
#define SM_CA  82176      // 256 floats
#define SM_CB  83200      // 256 floats
#define SM_RED 84224      // 128 floats
#define SM_FIN 84736      // 3*64 floats
#define SM_FLG 85504      // 4B
#define SM_TOT 85568

__device__ float g_acc[128];
__device__ unsigned int g_ctr = 0;

__device__ __forceinline__ float fexp(float x){
    x = fmaxf(fminf(x, 30.f), -30.f);
    return __expf(x);
}
__device__ __forceinline__ float sigf(float x){
    return __fdividef(1.0f, 1.0f + fexp(-x));
}
__device__ __forceinline__ float tanhp(float x){
    return 2.0f * __fdividef(1.0f, 1.0f + fexp(-2.0f*x)) - 1.0f;
}
__device__ __forceinline__ float tanha(float x){
    float r; asm("tanh.approx.f32 %0, %1;" : "=f"(r) : "f"(x)); return r;
}
__device__ __forceinline__ float siga(float x){
    return fmaf(0.5f, tanha(0.5f*x), 0.5f);
}

__device__ __forceinline__ void mma_fp16(float* c, const u32* a, const u32* b){
    asm volatile("mma.sync.aligned.m16n8k16.row.col.f32.f16.f16.f32 "
        "{%0,%1,%2,%3}, {%4,%5,%6,%7}, {%8,%9}, {%0,%1,%2,%3};\n"
        : "+f"(c[0]),"+f"(c[1]),"+f"(c[2]),"+f"(c[3])
        : "r"(a[0]),"r"(a[1]),"r"(a[2]),"r"(a[3]), "r"(b[0]),"r"(b[1]));
}

// ---------- single fused kernel, weight-stationary ----------
__global__ void __launch_bounds__(NTHR,1)
lstm_kernel(const float* __restrict__ x,
            const float* __restrict__ W_num,  const float* __restrict__ b_num,
            const float* __restrict__ W_ih,   const float* __restrict__ W_hh,
            const float* __restrict__ b_ih,   const float* __restrict__ b_hh,
            const float* __restrict__ W_aout, const float* __restrict__ b_aout,
            const float* __restrict__ W_fh,   const float* __restrict__ b_fh,
            const float* __restrict__ W_iouh, const float* __restrict__ b_iouh,
            const float* __restrict__ W_oout, const float* __restrict__ b_oout,
            float* __restrict__ out){
    extern __shared__ char sm[];
    const int tid  = threadIdx.x;
    const int wid  = tid >> 5;
    const int lane = tid & 31;
    const int g    = lane >> 2;      // group 0..7
    const int tq   = lane & 3;       // quad  0..3
    const int mtp  = wid & 1;        // m-pair: rows mtp*32 ..
    const int wn   = wid >> 1;       // n 32-col chunk 0..7
    const u32 xorv = (u32)g << 4;
    const int r0   = blockIdx.x * MROWS;

    float* sXf = (float*)(sm + SM_X);
    float* sCa = (float*)(sm + SM_CA);
    float* sCb = (float*)(sm + SM_CB);
    float* sRd = (float*)(sm + SM_RED);

    // ---- per-CTA prep ----
    // Column order: n = wn2*32 + j*8 + c; gate = j; d = wn2*8 + c; W row = j*64 + d.
    if (tid < 256){
        int n = tid;
        int wn2 = n >> 5;
        int j = (n >> 3) & 3;
        int c = n & 7;
        int d  = wn2*8 + c;
        int wr = j*64 + d;
        float sa = 0.f, sc = 0.f;
        #pragma unroll 8
        for (int k = 0; k < DD; k++){
            float w = __ldg(W_ih + wr*(2*DD) + k);
            sa += w * __ldg(W_num + k);
            sc += w * __ldg(b_num + k);
        }
        sCa[n] = sa;
        sCb[n] = sc + __ldg(b_ih + wr) + __ldg(b_hh + wr);
        #pragma unroll 8
        for (int k = 0; k < DD; k++){
            float w = __ldg(W_hh + wr*DD + k);
            u32 off = (u32)n*128 + (u32)k*2;
            u32 sw  = off ^ (((u32)n & 7u) << 4);
            *(__half*)(sm + SM_BH + sw) = __float2half_rn(w);
        }
    }
    {
        uint4 z = make_uint4(0,0,0,0);
        uint4* da = (uint4*)(sm + SM_A0);
        for (int i = tid; i < 1024; i += NTHR) da[i] = z;   // A0+A1 (16KB)
        for (int idx = tid; idx < MROWS*LL; idx += NTHR){
            int rr = idx >> 7, tt = idx & 127;
            sXf[rr*129 + tt] = x[(size_t)(r0 + rr)*LL + tt];
        }
        if (tid < 128) sRd[tid] = 0.f;
    }
    __syncthreads();

    // ---- pre-load this warp's B fragments into registers (stationary) ----
    u32 breg[4][4][2];
    {
        const char* Bh0 = sm + SM_BH + (size_t)((wn*32 + g) * 128);
        #pragma unroll
        for (int k4 = 0; k4 < 4; k4++){
            u32 o0 = ((u32)(32*k4 + 4*tq)) ^ xorv;
            u32 o8 = o0 ^ 16u;
            #pragma unroll
            for (int j = 0; j < 4; j++){
                breg[j][k4][0] = *(const u32*)(Bh0 + j*1024 + o0);
                breg[j][k4][1] = *(const u32*)(Bh0 + j*1024 + o8);
            }
        }
    }

    float creg[8];
    #pragma unroll
    for (int i = 0; i < 8; i++) creg[i] = 0.f;

    for (int t = 0; t < LL; t++){
        const char* Ah = sm + ((t & 1) ? SM_A1 : SM_A0);
        char* Aw = sm + ((t & 1) ? SM_A0 : SM_A1);
        const char* ArH = Ah + mtp*4096 + g*128;

        float acc[32];
        #pragma unroll
        for (int i = 0; i < 32; i++) acc[i] = 0.f;

        #pragma unroll
        for (int k4 = 0; k4 < 4; k4++){
            u32 o0 = ((u32)(32*k4 + 4*tq)) ^ xorv;
            u32 o8 = o0 ^ 16u;
            u32 a0[4], a1[4];
            a0[0] = *(const u32*)(ArH +        o0);
            a0[1] = *(const u32*)(ArH + 1024 + o0);
            a0[2] = *(const u32*)(ArH +        o8);
            a0[3] = *(const u32*)(ArH + 1024 + o8);
            a1[0] = *(const u32*)(ArH + 2048 +        o0);
            a1[1] = *(const u32*)(ArH + 2048 + 1024 + o0);
            a1[2] = *(const u32*)(ArH + 2048 +        o8);
            a1[3] = *(const u32*)(ArH + 2048 + 1024 + o8);
            #pragma unroll
            for (int j = 0; j < 4; j++){
                mma_fp16(acc +      j*4, a0, breg[j][k4]);
                mma_fp16(acc + 16 + j*4, a1, breg[j][k4]);
            }
        }

        // ---- epilogue: gates -> (c,h), write h fp16 ----
        float2 aJ[4], cJ[4];
        #pragma unroll
        for (int j = 0; j < 4; j++){
            int nI = wn*32 + j*8 + 2*tq;
            aJ[j] = *(const float2*)(sCa + nI);
            cJ[j] = *(const float2*)(sCb + nI);
        }
        const u32 cbS = ((u32)(wn*16 + 4*tq)) ^ xorv;
        #pragma unroll
        for (int sub = 0; sub < 2; sub++){
            #pragma unroll
            for (int s = 0; s < 2; s++){
                int r = mtp*32 + sub*16 + g + s*8;
                float xv = sXf[r*129 + t];
                float h2[2];
                #pragma unroll
                for (int u = 0; u < 2; u++){
                    int fi = s*2 + u;
                    float gi = acc[sub*16 +  0 + fi] + (u?aJ[0].y:aJ[0].x)*xv + (u?cJ[0].y:cJ[0].x);
                    float gf = acc[sub*16 +  4 + fi] + (u?aJ[1].y:aJ[1].x)*xv + (u?cJ[1].y:cJ[1].x);
                    float gg = acc[sub*16 +  8 + fi] + (u?aJ[2].y:aJ[2].x)*xv + (u?cJ[2].y:cJ[2].x);
                    float go = acc[sub*16 + 12 + fi] + (u?aJ[3].y:aJ[3].x)*xv + (u?cJ[3].y:cJ[3].x);
                    int ci = sub*4 + s*2 + u;
                    float c2 = siga(gf)*creg[ci] + siga(gi)*tanha(gg);
                    creg[ci] = c2;
                    h2[u] = siga(go)*tanha(c2);
                }
                __half b0 = __float2half_rn(h2[0]);
                __half b1 = __float2half_rn(h2[1]);
                u32 hp = (u32)__half_as_ushort(b0) | ((u32)__half_as_ushort(b1) << 16);
                *(u32*)(Aw + r*128 + cbS) = hp;
            }
        }
        __syncthreads();
    }

    // ---- final per-CTA stage ----
    float* sHfin = (float*)(sm + SM_X);            // [row][d] stride 64
    float* sCst  = (float*)(sm + SM_X + 16384);
    #pragma unroll
    for (int sub = 0; sub < 2; sub++){
        #pragma unroll
        for (int s = 0; s < 2; s++){
            #pragma unroll
            for (int u = 0; u < 2; u++){
                int r = mtp*32 + sub*16 + g + s*8;
                int d = wn*8 + 2*tq + u;
                u32 sw = ((u32)(2*d)) ^ xorv;
                float h = __half2float(*(const __half*)(sm + SM_A0 + r*128 + sw));
                sHfin[r*64 + d] = h;
                sCst [r*64 + d] = creg[sub*4 + s*2 + u];
            }
        }
    }
    float* sWa = (float*)(sm + SM_BH);
    float* sWf = sWa + 4096;
    for (int i = tid; i < 4096; i += NTHR){ sWa[i] = W_aout[i]; sWf[i] = W_fh[i]; }
    __syncthreads();

    float* sHhat = (float*)(sm + SM_A0);           // [row][d] stride 64 (16KB = A0+A1)
    const int row = tid >> 3;
    const int d0  = (tid & 7) << 3;
    #pragma unroll 2
    for (int jj = 0; jj < 8; jj++){
        int d = d0 + jj;
        float acc2 = __ldg(b_aout + d);
        #pragma unroll 8
        for (int e = 0; e < DD; e++) acc2 += sHfin[row*64 + e] * sWa[d*64 + e];
        sHhat[row*64 + d] = acc2;
        atomicAdd(&sRd[64 + d], acc2);
    }
    __syncthreads();
    #pragma unroll 2
    for (int jj = 0; jj < 8; jj++){
        int d = d0 + jj;
        float f = __ldg(b_fh + d);
        #pragma unroll 8
        for (int e = 0; e < DD; e++) f += sHhat[row*64 + e] * sWf[d*64 + e];
        atomicAdd(&sRd[d], sigf(f) * sCst[row*64 + d]);
    }
    __syncthreads();

    // ---- global reduction + last-CTA finisher ----
    if (tid < 128) atomicAdd(&g_acc[tid], sRd[tid]);
    __threadfence();
    __syncthreads();
    if (tid == 0){
        unsigned int rnk = atomicAdd(&g_ctr, 1);
        *(u32*)(sm + SM_FLG) = (rnk == NBLK - 1) ? 1u : 0u;
    }
    __syncthreads();
    if (*(const u32*)(sm + SM_FLG)){
        float* sfc = (float*)(sm + SM_FIN);
        float* shs = sfc + 64;
        float* sho = sfc + 128;
        if (tid < 64){ sfc[tid] = g_acc[tid]; shs[tid] = g_acc[64 + tid]; }
        __syncthreads();
        if (tid < 64){
            int d = tid;
            float vi = __ldg(b_iouh + d), vo = __ldg(b_iouh + 64 + d), vu = __ldg(b_iouh + 128 + d);
            #pragma unroll 8
            for (int e = 0; e < DD; e++){
                float h = shs[e];
                vi += h * __ldg(W_iouh + (      d)*64 + e);
                vo += h * __ldg(W_iouh + ( 64 + d)*64 + e);
                vu += h * __ldg(W_iouh + (128 + d)*64 + e);
            }
            float cobj = sigf(vi)*tanhp(vu) + sfc[d];
            sho[d] = sigf(vo)*tanhp(cobj);
            out[64 + d] = cobj;
        }
        __syncthreads();
        if (tid < 64){
            int d = tid;
            float acc3 = __ldg(b_oout + d);
            #pragma unroll 8
            for (int e = 0; e < DD; e++) acc3 += sho[e] * __ldg(W_oout + d*64 + e);
            out[d] = acc3;
        }
        if (tid < 128) g_acc[tid] = 0.f;
        __threadfence();
        if (tid == 0) g_ctr = 0;
    }
}

extern "C" void kernel_launch(void* const* d_in, const int* in_sizes, int n_in,
                              void* d_out, int out_size){
    const float* x      = (const float*)d_in[0];
    const float* W_num  = (const float*)d_in[1];
    const float* b_num  = (const float*)d_in[2];
    const float* W_ih   = (const float*)d_in[3];
    const float* W_hh   = (const float*)d_in[4];
    const float* b_ih   = (const float*)d_in[5];
    const float* b_hh   = (const float*)d_in[6];
    const float* W_aout = (const float*)d_in[7];
    const float* b_aout = (const float*)d_in[8];
    const float* W_fh   = (const float*)d_in[9];
    const float* b_fh   = (const float*)d_in[10];
    const float* W_iouh = (const float*)d_in[11];
    const float* b_iouh = (const float*)d_in[12];
    const float* W_oout = (const float*)d_in[13];
    const float* b_oout = (const float*)d_in[14];
    float* out = (float*)d_out;

    cudaFuncSetAttribute(lstm_kernel, cudaFuncAttributeMaxDynamicSharedMemorySize, SM_TOT);

    lstm_kernel<<<NBLK, NTHR, SM_TOT>>>(x, W_num, b_num, W_ih, W_hh, b_ih, b_hh,
                                        W_aout, b_aout, W_fh, b_fh,
                                        W_iouh, b_iouh, W_oout, b_oout, out);
}